// round 3
// baseline (speedup 1.0000x reference)
#include <cuda_runtime.h>

// NCM R3: 4 output-cols per lane (2x16-lane groups per warp), bank-disjoint
// group act buffers, transposed w3. Cuts L1 wavefronts per FFMA2 by ~1.67x.

#define TPB   256
#define NBLK  128
#define NNODES 32

typedef unsigned long long u64;
typedef unsigned int u32;

__device__ __forceinline__ u64 fma2(u64 a, u64 b, u64 c) {
    u64 d; asm("fma.rn.f32x2 %0,%1,%2,%3;" : "=l"(d) : "l"(a), "l"(b), "l"(c));
    return d;
}
__device__ __forceinline__ u64 dup2(float x) {
    u64 d; asm("mov.b64 %0,{%1,%1};" : "=l"(d) : "f"(x)); return d;
}
__device__ __forceinline__ void unpk(u64 a, float& lo, float& hi) {
    asm("mov.b64 {%0,%1},%2;" : "=f"(lo), "=f"(hi) : "l"(a));
}
__device__ __forceinline__ u64 pk(float lo, float hi) {
    u64 d; asm("mov.b64 %0,{%1,%2};" : "=l"(d) : "f"(lo), "f"(hi)); return d;
}
__device__ __forceinline__ u64 relu2(u64 a) {
    float lo, hi; unpk(a, lo, hi);
    return pk(fmaxf(lo, 0.0f), fmaxf(hi, 0.0f));
}

// float region (floats): w1[80][64] | w2[64][64] | w3T[16][66] | b1 b2 b3
#define OFF_W2  5120
#define OFF_W3T 9216
#define OFF_B1  10272
#define OFF_B2  10336
#define OFF_B3  10400
#define WOFF    10416                 // 41664 bytes, 16B aligned

// per-warp u64 region:
//   in:  group0 [8][80] | pad 8 | group1 [8][80]   (rows: 0..63 ring, 64..79 u)
//   h:   group0 [8][64] | pad 8 | group1 [8][64]
#define IN_STR 80
#define H_STR  64
#define IN_GOFF (8 * IN_STR + 8)      // 648 (word delta %32 == 16 -> disjoint banks)
#define H_GOFF  (8 * H_STR + 8)       // 520
#define IN_TOT  (IN_GOFF + 8 * IN_STR)  // 1288
#define H_TOT   (H_GOFF + 8 * H_STR)    // 1032
#define WARP_U64 (IN_TOT + H_TOT)       // 2320
#define SMEM_BYTES (WOFF * 4 + 8 * WARP_U64 * 8)   // 190144

__global__ void __launch_bounds__(TPB, 1) ncm_kernel(
    const float* __restrict__ u,
    const float* __restrict__ w_r1, const float* __restrict__ b_r1,
    const float* __restrict__ w_r2, const float* __restrict__ b_r2,
    const float* __restrict__ w_r3, const float* __restrict__ b_r3,
    const float* __restrict__ w_i1, const float* __restrict__ b_i1,
    const float* __restrict__ w_i2, const float* __restrict__ b_i2,
    const float* __restrict__ w_i3, const float* __restrict__ b_i3,
    float* __restrict__ out)
{
    extern __shared__ float smem[];
    float* s_w1  = smem;
    float* s_w2  = smem + OFF_W2;
    float* s_w3T = smem + OFF_W3T;
    float* s_b1  = smem + OFF_B1;
    float* s_b2  = smem + OFF_B2;
    float* s_b3  = smem + OFF_B3;

    const int tid = threadIdx.x;
    const int wp = tid >> 5, l = tid & 31;
    const int h = l >> 4;        // 16-lane group
    const int t = l & 15;        // lane-in-group: owns cols 4t..4t+3 (L1/L2), col t (L3)

    u64* warp_u = (u64*)(smem + WOFF) + wp * WARP_U64;
    u64* s_in_g = warp_u + h * IN_GOFF;            // this group's [8][80]
    u64* s_h_g  = warp_u + IN_TOT + h * H_GOFF;    // this group's [8][64]

    const long sbase = (long)blockIdx.x * TPB + wp * 32;

    u64 acc[32];   // [pair p][col c] = acc[p*4+c]

    for (int node = 0; node < NNODES; ++node) {
        const bool root = (node < 4);
        const float *g1, *g2, *g3, *gb1, *gb2, *gb3;
        if (root) {
            g1 = w_r1 + node * (16 * 64);
            g2 = w_r2 + node * (64 * 64);
            g3 = w_r3 + node * (64 * 16);
            gb1 = b_r1 + node * 64; gb2 = b_r2 + node * 64; gb3 = b_r3 + node * 16;
        } else {
            const int j = node - 4;
            g1 = w_i1 + j * (80 * 64);
            g2 = w_i2 + j * (64 * 64);
            g3 = w_i3 + j * (64 * 16);
            gb1 = b_i1 + j * 64; gb2 = b_i2 + j * 64; gb3 = b_i3 + j * 16;
        }

        __syncthreads();   // all warps done with previous node's weights

        // ---- stage weights (coalesced float4); w3 transposed with stride 66 ----
        {
            const int n1 = root ? (16 * 64 / 4) : (80 * 64 / 4);
            for (int i = tid; i < n1; i += TPB)
                ((float4*)s_w1)[i] = ((const float4*)g1)[i];
            for (int i = tid; i < 64 * 64 / 4; i += TPB)
                ((float4*)s_w2)[i] = ((const float4*)g2)[i];
            for (int i = tid; i < 64 * 16; i += TPB) {
                const int k = i >> 4, c = i & 15;
                s_w3T[c * 66 + k] = g3[i];
            }
            if (tid < 64) { s_b1[tid] = gb1[tid]; s_b2[tid] = gb2[tid]; }
            if (tid < 16) s_b3[tid] = gb3[tid];
        }
        // ---- stage u slice: lane l -> sample sbase+l -> [group][pair][64+d] ----
        {
            const float* up = u + (sbase + l) * (NNODES * 16) + node * 16;
            // lane's sample belongs to group l>>4 == h, pair (l>>1)&7, half l&1
            float* inf = (float*)(s_in_g + ((l >> 1) & 7) * IN_STR + 64);
            const int c = l & 1;
            #pragma unroll
            for (int dd = 0; dd < 16; dd += 4) {
                float4 v4 = *(const float4*)(up + dd);
                inf[(dd + 0) * 2 + c] = v4.x;
                inf[(dd + 1) * 2 + c] = v4.y;
                inf[(dd + 2) * 2 + c] = v4.z;
                inf[(dd + 3) * 2 + c] = v4.w;
            }
        }
        __syncthreads();

        // inner block: W rows wrow.. (4 cols at 4t), acts at act[p*stride + kk]
        auto mm = [&](const float* W, int wrow, const u64* act, int stride,
                      int kcount) {
            #pragma unroll 1
            for (int kk = 0; kk < kcount; kk += 2) {
                float4 wa = *(const float4*)(W + (wrow + kk) * 64 + 4 * t);
                float4 wb = *(const float4*)(W + (wrow + kk + 1) * 64 + 4 * t);
                const u64 A0 = dup2(wa.x), A1 = dup2(wa.y),
                          A2 = dup2(wa.z), A3 = dup2(wa.w);
                const u64 B0 = dup2(wb.x), B1 = dup2(wb.y),
                          B2 = dup2(wb.z), B3 = dup2(wb.w);
                #pragma unroll
                for (int p = 0; p < 8; ++p) {
                    ulonglong2 xx = *(const ulonglong2*)(act + p * stride + kk);
                    acc[p * 4 + 0] = fma2(xx.x, A0, acc[p * 4 + 0]);
                    acc[p * 4 + 1] = fma2(xx.x, A1, acc[p * 4 + 1]);
                    acc[p * 4 + 2] = fma2(xx.x, A2, acc[p * 4 + 2]);
                    acc[p * 4 + 3] = fma2(xx.x, A3, acc[p * 4 + 3]);
                    acc[p * 4 + 0] = fma2(xx.y, B0, acc[p * 4 + 0]);
                    acc[p * 4 + 1] = fma2(xx.y, B1, acc[p * 4 + 1]);
                    acc[p * 4 + 2] = fma2(xx.y, B2, acc[p * 4 + 2]);
                    acc[p * 4 + 3] = fma2(xx.y, B3, acc[p * 4 + 3]);
                }
            }
        };

        auto relu_store = [&]() {
            #pragma unroll
            for (int p = 0; p < 8; ++p) {
                ulonglong2 r0, r1;
                r0.x = relu2(acc[p * 4 + 0]); r0.y = relu2(acc[p * 4 + 1]);
                r1.x = relu2(acc[p * 4 + 2]); r1.y = relu2(acc[p * 4 + 3]);
                *(ulonglong2*)(s_h_g + p * H_STR + 4 * t)     = r0;
                *(ulonglong2*)(s_h_g + p * H_STR + 4 * t + 2) = r1;
            }
        };

        // ---- layer 1 ----
        {
            float4 bb = *(const float4*)(s_b1 + 4 * t);
            const u64 i0 = dup2(bb.x), i1 = dup2(bb.y),
                      i2 = dup2(bb.z), i3 = dup2(bb.w);
            #pragma unroll
            for (int p = 0; p < 8; ++p) {
                acc[p * 4 + 0] = i0; acc[p * 4 + 1] = i1;
                acc[p * 4 + 2] = i2; acc[p * 4 + 3] = i3;
            }
        }
        if (!root) {
            #pragma unroll 1
            for (int q = 0; q < 4; ++q)
                mm(s_w1, q * 16, s_in_g + ((node + q) & 3) * 16, IN_STR, 16);
            mm(s_w1, 64, s_in_g + 64, IN_STR, 16);
        } else {
            mm(s_w1, 0, s_in_g + 64, IN_STR, 16);
        }
        relu_store();
        __syncwarp();

        // ---- layer 2 (in-place h; all reads precede writes via syncwarp) ----
        {
            float4 bb = *(const float4*)(s_b2 + 4 * t);
            const u64 i0 = dup2(bb.x), i1 = dup2(bb.y),
                      i2 = dup2(bb.z), i3 = dup2(bb.w);
            #pragma unroll
            for (int p = 0; p < 8; ++p) {
                acc[p * 4 + 0] = i0; acc[p * 4 + 1] = i1;
                acc[p * 4 + 2] = i2; acc[p * 4 + 3] = i3;
            }
        }
        mm(s_w2, 0, s_h_g, H_STR, 64);
        __syncwarp();
        relu_store();
        __syncwarp();

        // ---- layer 3: lane owns single col t; transposed w3 (stride 66) ----
        u64 c3[8];
        {
            const u64 bt = dup2(s_b3[t]);
            #pragma unroll
            for (int p = 0; p < 8; ++p) c3[p] = bt;
        }
        #pragma unroll 1
        for (int kk = 0; kk < 64; kk += 2) {
            float2 w2v = *(const float2*)(s_w3T + t * 66 + kk);
            const u64 A = dup2(w2v.x), B = dup2(w2v.y);
            #pragma unroll
            for (int p = 0; p < 8; ++p) {
                ulonglong2 xx = *(const ulonglong2*)(s_h_g + p * H_STR + kk);
                c3[p] = fma2(xx.x, A, c3[p]);
                c3[p] = fma2(xx.y, B, c3[p]);
            }
        }

        // ---- emit: logits to gmem, thresholded bits into parent ring ----
        const int slot = (node & 3) * 16;
        const long srow = sbase + 16 * h;
        #pragma unroll
        for (int p = 0; p < 8; ++p) {
            float v0, v1; unpk(c3[p], v0, v1);
            out[(srow + 2 * p)     * (NNODES * 16) + node * 16 + t] = v0;
            out[(srow + 2 * p + 1) * (NNODES * 16) + node * 16 + t] = v1;
            s_in_g[p * IN_STR + slot + t] =
                pk(v0 > 0.5f ? 1.0f : 0.0f, v1 > 0.5f ? 1.0f : 0.0f);
        }
        __syncwarp();
    }
}

extern "C" void kernel_launch(void* const* d_in, const int* in_sizes, int n_in,
                              void* d_out, int out_size) {
    (void)in_sizes; (void)n_in; (void)out_size;
    cudaFuncSetAttribute(ncm_kernel, cudaFuncAttributeMaxDynamicSharedMemorySize,
                         SMEM_BYTES);
    ncm_kernel<<<NBLK, TPB, SMEM_BYTES>>>(
        (const float*)d_in[0],
        (const float*)d_in[1], (const float*)d_in[2],
        (const float*)d_in[3], (const float*)d_in[4],
        (const float*)d_in[5], (const float*)d_in[6],
        (const float*)d_in[7], (const float*)d_in[8],
        (const float*)d_in[9], (const float*)d_in[10],
        (const float*)d_in[11], (const float*)d_in[12],
        (float*)d_out);
}